// round 15
// baseline (speedup 1.0000x reference)
#include <cuda_runtime.h>
#include <cuda_bf16.h>
#include <stdint.h>

#define BB 32
#define SS 2048
#define HH 1024
#define MTOT (BB*SS)
#define NT 8            // 128-wide o-tiles
#define KC 32           // k per stage (bf16)
#define NKT (HH/KC)     // 32
#define SCH 16          // context s-chunks

// smem: A hi/lo 2-stage ring (16KB/stage), B hi/lo 4-stage ring (16KB/stage)
#define HALF 8192                   // one 128x32 bf16 tile (64B rows)
#define A_STAGE 16384               // Ah+Al
#define B_BASE  32768
#define B_STAGE 16384               // Bh+Bl
#define OF_VA   98304
#define OF_QC   (OF_VA+512)
#define OF_PART (OF_QC+512)
#define GEMM_SMEM (OF_PART+1024)    // 100352

#define SWZ(o) ((o) ^ (((o) >> 3) & 0x70))

// ---------------- device scratch (no allocs allowed) ----------------
__device__ float g_qc[BB*HH];
__device__ float g_part[NT][MTOT];
__device__ float g_cpart[SCH][BB][HH];
__device__ __nv_bfloat16 g_uhi[HH*HH];
__device__ __nv_bfloat16 g_ulo[HH*HH];

// ---------------- helpers ----------------
__device__ __forceinline__ uint32_t smem_u32(const void* p) {
    uint32_t a;
    asm("{ .reg .u64 t; cvta.to.shared.u64 t, %1; cvt.u32.u64 %0, t; }" : "=r"(a) : "l"(p));
    return a;
}
__device__ __forceinline__ void ldsm4(uint32_t a, uint32_t& r0, uint32_t& r1,
                                      uint32_t& r2, uint32_t& r3) {
    asm volatile("ldmatrix.sync.aligned.m8n8.x4.shared.b16 {%0,%1,%2,%3}, [%4];"
                 : "=r"(r0), "=r"(r1), "=r"(r2), "=r"(r3) : "r"(a));
}
__device__ __forceinline__ void mma16816(float* d, const uint32_t* a, uint32_t b0, uint32_t b1) {
    asm volatile("mma.sync.aligned.m16n8k16.row.col.f32.bf16.bf16.f32 "
                 "{%0,%1,%2,%3}, {%4,%5,%6,%7}, {%8,%9}, {%0,%1,%2,%3};"
                 : "+f"(d[0]), "+f"(d[1]), "+f"(d[2]), "+f"(d[3])
                 : "r"(a[0]), "r"(a[1]), "r"(a[2]), "r"(a[3]), "r"(b0), "r"(b1));
}
// flag-independent tanh: 1 - 2/(1+e^{2x}); exact saturation at +/-inf.
__device__ __forceinline__ float tanh_fast(float x) {
    float e;
    asm("ex2.approx.f32 %0, %1;" : "=f"(e) : "f"(x * 2.8853900817779268f));
    return 1.f - __fdividef(2.f, 1.f + e);
}
// pack two fp32 -> (bf16 hi pair, bf16 lo pair)
__device__ __forceinline__ void hilo2(float x, float y, uint32_t& hp, uint32_t& lp) {
    uint32_t h;
    asm("cvt.rn.bf16x2.f32 %0, %1, %2;" : "=r"(h) : "f"(y), "f"(x));  // {hi=y, lo=x}
    float hx = __uint_as_float(h << 16);
    float hy = __uint_as_float(h & 0xFFFF0000u);
    float lx = x - hx, ly = y - hy;
    uint32_t l;
    asm("cvt.rn.bf16x2.f32 %0, %1, %2;" : "=r"(l) : "f"(ly), "f"(lx));
    hp = h; lp = l;
}

// ---------------- kernel 0: Ua fp32 -> bf16 hi/lo split (4MB) --------------
__global__ void split_ua_kernel(const float* __restrict__ src) {
    int i = blockIdx.x * 256 + threadIdx.x;
    float4 v = ((const float4*)src)[i];
    uint2 ph, pl;
    hilo2(v.x, v.y, ph.x, pl.x);
    hilo2(v.z, v.w, ph.y, pl.y);
    ((uint2*)g_uhi)[i] = ph;
    ((uint2*)g_ulo)[i] = pl;
}

// ---------------- kernel 1: qc[b,o] = dec@Wa^T + Wa_b + Ua_b ----------------
// Tiled: 128 blocks x 8 warps; warp = one o, all 32 b. dec streamed through
// smem in 256-col chunks (conflict-free: bank = lane). Wa read exactly once.
__global__ __launch_bounds__(256)
void qc_kernel(const float* __restrict__ dec,
               const float* __restrict__ Wa_w,
               const float* __restrict__ Wa_b,
               const float* __restrict__ Ua_b) {
    __shared__ float sdec[32][256];   // 32KB
    const int tid = threadIdx.x, wid = tid >> 5, lane = tid & 31;
    const int o = blockIdx.x * 8 + wid;

    float acc[32];
    #pragma unroll
    for (int b = 0; b < 32; ++b) acc[b] = 0.f;

    for (int c = 0; c < 4; ++c) {
        #pragma unroll
        for (int v = 0; v < 8; ++v) {          // 2048 float4 / 256 threads
            int li = tid + v * 256;
            int r = li >> 6, col = (li * 4) & 255;
            *(float4*)&sdec[r][col] = *(const float4*)(dec + r * HH + c * 256 + col);
        }
        __syncthreads();
        float wa[8];
        #pragma unroll
        for (int j = 0; j < 8; ++j) wa[j] = Wa_w[o * HH + c * 256 + j * 32 + lane];
        #pragma unroll
        for (int j = 0; j < 8; ++j)
            #pragma unroll
            for (int b = 0; b < 32; ++b)
                acc[b] = fmaf(sdec[b][j * 32 + lane], wa[j], acc[b]);
        __syncthreads();
    }
    #pragma unroll
    for (int off = 16; off; off >>= 1)
        #pragma unroll
        for (int b = 0; b < 32; ++b)
            acc[b] += __shfl_xor_sync(0xffffffffu, acc[b], off);
    if (lane == 0) {
        float bias = Wa_b[o] + Ua_b[o];
        #pragma unroll
        for (int b = 0; b < 32; ++b) g_qc[b * HH + o] = acc[b] + bias;
    }
}

// ---------------- kernel 2: HMMA energy GEMM (bf16x3, fused A split) --------
// UNCHANGED from the 947us winner.
__global__ __launch_bounds__(256, 2)
void energy_gemm_hmma(const float* __restrict__ enc, const float* __restrict__ Va) {
    extern __shared__ __align__(1024) char smem[];
    uint32_t sb = smem_u32(smem);
    const int tid = threadIdx.x, wid = tid >> 5, lane = tid & 31;
    const int ot = blockIdx.x, m0 = blockIdx.y * 128, o0 = ot * 128;
    const int b = m0 >> 11;                 // / SS
    const int wm = wid & 3, wn = wid >> 2;  // warp grid 4x2
    const int tT = lane >> 3, r8 = lane & 7;

    if (tid < 128) {
        ((float*)(smem + OF_VA))[tid] = Va[o0 + tid];
        ((float*)(smem + OF_QC))[tid] = g_qc[b * HH + o0 + tid];
    }

    const float* gA = enc + (size_t)m0 * HH;          // fp32 A panel
    const __nv_bfloat16* gBh = g_uhi + (size_t)o0 * HH;
    const __nv_bfloat16* gBl = g_ulo + (size_t)o0 * HH;

    const int ar[4] = { (tid + 0) >> 3, (tid + 256) >> 3, (tid + 512) >> 3, (tid + 768) >> 3 };
    const int ac4   =  tid & 7;

    auto ldgA = [&](int kt, float4* regs) {
        #pragma unroll
        for (int t = 0; t < 4; ++t)
            regs[t] = *(const float4*)(gA + (size_t)ar[t] * HH + kt * KC + ac4 * 4);
    };
    auto stsA = [&](int st, const float4* regs) {
        uint32_t base = sb + st * A_STAGE;
        #pragma unroll
        for (int t = 0; t < 4; ++t) {
            uint32_t off = SWZ((uint32_t)(ar[t] * 64 + (ac4 >> 1) * 16)) + (ac4 & 1) * 8;
            uint32_t h0, l0, h1, l1;
            hilo2(regs[t].x, regs[t].y, h0, l0);
            hilo2(regs[t].z, regs[t].w, h1, l1);
            asm volatile("st.shared.v2.b32 [%0], {%1,%2};" :: "r"(base + off), "r"(h0), "r"(h1) : "memory");
            asm volatile("st.shared.v2.b32 [%0], {%1,%2};" :: "r"(base + HALF + off), "r"(l0), "r"(l1) : "memory");
        }
    };
    auto issueB = [&](int st4, int kt) {
        #pragma unroll
        for (int t = 0; t < 4; ++t) {
            const int arr = t >> 1;                     // 0: Bh, 1: Bl
            int idx = ((t & 1) << 8) + tid;             // 0..511 per tile
            int r = idx >> 2, c = idx & 3;
            const __nv_bfloat16* g = (arr ? gBl : gBh) + (size_t)r * HH + kt * KC + c * 8;
            uint32_t s = sb + B_BASE + st4 * B_STAGE + arr * HALF + SWZ((uint32_t)(r * 64 + c * 16));
            asm volatile("cp.async.cg.shared.global [%0], [%1], 16;" :: "r"(s), "l"(g));
        }
        asm volatile("cp.async.commit_group;" ::: "memory");
    };

    float acc[2][8][4];
    #pragma unroll
    for (int i = 0; i < 2; ++i)
        #pragma unroll
        for (int j = 0; j < 8; ++j)
            #pragma unroll
            for (int k = 0; k < 4; ++k) acc[i][j][k] = 0.f;

    float4 aReg[4];
    ldgA(0, aReg);
    issueB(0, 0);
    stsA(0, aReg);          // A(0) into buf 0 (published by loop's first barrier)
    ldgA(1, aReg);
    issueB(1, 1);
    issueB(2, 2);

    for (int kt = 0; kt < NKT; ++kt) {
        asm volatile("cp.async.wait_group 2;" ::: "memory");
        __syncthreads();   // publish A(kt)+B(kt); all warps past compute(kt-1)
        if (kt + 3 < NKT)
            issueB((kt + 3) & 3, kt + 3);
        else
            asm volatile("cp.async.commit_group;" ::: "memory");  // keep group math exact

        uint32_t stbA = sb + (uint32_t)(kt & 1) * A_STAGE;
        uint32_t stbB = sb + B_BASE + (uint32_t)(kt & 3) * B_STAGE;

        auto computeHalf = [&](int kk) {
            uint32_t ah[2][4], al[2][4];
            #pragma unroll
            for (int mb = 0; mb < 2; ++mb) {
                uint32_t row  = wm * 32 + mb * 16 + (tT & 1) * 8 + r8;
                uint32_t byte = row * 64 + (kk * 16 + (tT >> 1) * 8) * 2;
                ldsm4(stbA + SWZ(byte), ah[mb][0], ah[mb][1], ah[mb][2], ah[mb][3]);
                ldsm4(stbA + HALF + SWZ(byte), al[mb][0], al[mb][1], al[mb][2], al[mb][3]);
            }
            uint32_t bh[2][4], bl[2][4];
            auto loadB = [&](int q, uint32_t* BH, uint32_t* BL) {
                uint32_t nrow = wn * 64 + q * 16 + (tT >> 1) * 8 + r8;
                uint32_t byte = nrow * 64 + (kk * 16 + (tT & 1) * 8) * 2;
                ldsm4(stbB + SWZ(byte), BH[0], BH[1], BH[2], BH[3]);
                ldsm4(stbB + HALF + SWZ(byte), BL[0], BL[1], BL[2], BL[3]);
            };
            loadB(0, bh[0], bl[0]);
            #pragma unroll
            for (int q = 0; q < 4; ++q) {
                if (q < 3) loadB(q + 1, bh[(q + 1) & 1], bl[(q + 1) & 1]);
                const uint32_t* BH = bh[q & 1];
                const uint32_t* BL = bl[q & 1];
                #pragma unroll
                for (int mb = 0; mb < 2; ++mb) {
                    mma16816(acc[mb][2 * q + 0], ah[mb], BH[0], BH[1]);   // Ah*Bh
                    mma16816(acc[mb][2 * q + 1], ah[mb], BH[2], BH[3]);
                    mma16816(acc[mb][2 * q + 0], ah[mb], BL[0], BL[1]);   // Ah*Bl
                    mma16816(acc[mb][2 * q + 1], ah[mb], BL[2], BL[3]);
                    mma16816(acc[mb][2 * q + 0], al[mb], BH[0], BH[1]);   // Al*Bh
                    mma16816(acc[mb][2 * q + 1], al[mb], BH[2], BH[3]);
                }
            }
        };
        computeHalf(0);
        // A staging mid-loop: off the barrier->MMA critical path. stsA(kt+1)
        // reads aReg BEFORE ldgA(kt+2) overwrites it (WAR order).
        if (kt + 1 < NKT) stsA((kt + 1) & 1, aReg);
        if (kt + 2 < NKT) ldgA(kt + 2, aReg);
        computeHalf(1);
    }

    // Fused epilogue: part[m] = sum_o Va[o]*tanh(acc + qc[o])
    const float* sva = (const float*)(smem + OF_VA);
    const float* sqc = (const float*)(smem + OF_QC);
    const int gid = lane >> 2, t4 = lane & 3;
    float pm[4] = {0.f, 0.f, 0.f, 0.f};
    #pragma unroll
    for (int mb = 0; mb < 2; ++mb)
        #pragma unroll
        for (int nb = 0; nb < 8; ++nb) {
            int o = wn * 64 + nb * 8 + t4 * 2;
            float va0 = sva[o], va1 = sva[o + 1];
            float q0 = sqc[o], q1 = sqc[o + 1];
            pm[mb * 2 + 0] += va0 * tanh_fast(acc[mb][nb][0] + q0)
                            + va1 * tanh_fast(acc[mb][nb][1] + q1);
            pm[mb * 2 + 1] += va0 * tanh_fast(acc[mb][nb][2] + q0)
                            + va1 * tanh_fast(acc[mb][nb][3] + q1);
        }
    #pragma unroll
    for (int off = 1; off <= 2; off <<= 1) {
        #pragma unroll
        for (int i = 0; i < 4; ++i) pm[i] += __shfl_xor_sync(0xffffffffu, pm[i], off);
    }
    float* sp = (float*)(smem + OF_PART);
    __syncthreads();
    if (t4 == 0) {
        #pragma unroll
        for (int mb = 0; mb < 2; ++mb) {
            sp[wn * 128 + wm * 32 + mb * 16 + gid]     = pm[mb * 2 + 0];
            sp[wn * 128 + wm * 32 + mb * 16 + 8 + gid] = pm[mb * 2 + 1];
        }
    }
    __syncthreads();
    if (tid < 128) g_part[ot][m0 + tid] = sp[tid] + sp[128 + tid];
}

// ---------------- kernel 3: sparsemax (sort-free, exact) ----------------
// 16 bisection iters bracket tau* (lo <= tau*), then 3 Michelot fixed-point
// refinements: support(lo) is a superset of the true support, and
// tau <- (sum_{z>tau} z - 1)/|{z>tau}| converges monotonically to tau*.
__global__ void sparsemax_kernel(const float* __restrict__ Va_b,
                                 float* __restrict__ wout) {
    __shared__ float z[SS];
    __shared__ float red[33];
    const int b = blockIdx.x;
    const int tid = threadIdx.x;
    const float vb = Va_b[0];

    for (int s = tid; s < SS; s += 256) {
        float e = vb;
        #pragma unroll
        for (int t = 0; t < NT; ++t) e += g_part[t][b * SS + s];
        z[s] = e;
    }
    __syncthreads();

    float mx = -3.4e38f;
    for (int s = tid; s < SS; s += 256) mx = fmaxf(mx, z[s]);
    #pragma unroll
    for (int off = 16; off; off >>= 1) mx = fmaxf(mx, __shfl_xor_sync(0xffffffffu, mx, off));
    if ((tid & 31) == 0) red[tid >> 5] = mx;
    __syncthreads();
    if (tid == 0) {
        float m = red[0];
        for (int i = 1; i < 8; ++i) m = fmaxf(m, red[i]);
        red[32] = m;
    }
    __syncthreads();
    const float zmax = red[32];
    __syncthreads();

    float lo = zmax - 1.f, hi = zmax;
    for (int it = 0; it < 16; ++it) {
        float mid = 0.5f * (lo + hi);
        float sum = 0.f;
        for (int s = tid; s < SS; s += 256) sum += fmaxf(z[s] - mid, 0.f);
        #pragma unroll
        for (int off = 16; off; off >>= 1) sum += __shfl_xor_sync(0xffffffffu, sum, off);
        if ((tid & 31) == 0) red[tid >> 5] = sum;
        __syncthreads();
        if (tid == 0) {
            float t = 0.f;
            for (int i = 0; i < 8; ++i) t += red[i];
            red[32] = t;
        }
        __syncthreads();
        float tot = red[32];
        __syncthreads();
        if (tot >= 1.f) lo = mid; else hi = mid;
    }
    float tau = lo;   // guaranteed <= tau*  -> support superset for refinement

    for (int r2 = 0; r2 < 3; ++r2) {
        float cnt = 0.f, ssum = 0.f;
        for (int s = tid; s < SS; s += 256) {
            float zv = z[s];
            if (zv > tau) { cnt += 1.f; ssum += zv; }
        }
        #pragma unroll
        for (int off = 16; off; off >>= 1) {
            cnt  += __shfl_xor_sync(0xffffffffu, cnt,  off);
            ssum += __shfl_xor_sync(0xffffffffu, ssum, off);
        }
        if ((tid & 31) == 0) { red[tid >> 5] = cnt; red[8 + (tid >> 5)] = ssum; }
        __syncthreads();
        if (tid == 0) {
            float c = 0.f, s2 = 0.f;
            for (int i = 0; i < 8; ++i) { c += red[i]; s2 += red[8 + i]; }
            red[32] = (s2 - 1.f) / c;
        }
        __syncthreads();
        tau = red[32];
        __syncthreads();
    }

    for (int s = tid; s < SS; s += 256)
        wout[b * SS + s] = fmaxf(z[s] - tau, 0.f);
}

// ---------------- kernel 4: context (S-chunked, sparse skip) ----------------
__global__ void context_part(const float* __restrict__ enc,
                             const float* __restrict__ w) {
    const int b = blockIdx.y, zc = blockIdx.z;
    const int h = blockIdx.x * 256 + threadIdx.x;
    const int SC = SS / SCH;
    const float* wr = w + b * SS + zc * SC;
    const float* e = enc + (size_t)b * SS * HH + (size_t)zc * SC * HH + h;
    float acc = 0.f;
    #pragma unroll 4
    for (int s = 0; s < SC; ++s) {
        float ws = wr[s];
        if (ws != 0.f) acc = fmaf(ws, e[(size_t)s * HH], acc);
    }
    g_cpart[zc][b][h] = acc;
}
__global__ void context_reduce(float* __restrict__ ctx) {
    int i = blockIdx.x * 256 + threadIdx.x;
    int b = i >> 10, h = i & 1023;
    float a = 0.f;
    #pragma unroll
    for (int zc = 0; zc < SCH; ++zc) a += g_cpart[zc][b][h];
    ctx[i] = a;
}

// ---------------------------------------------------------------------------
extern "C" void kernel_launch(void* const* d_in, const int* in_sizes, int n_in,
                              void* d_out, int out_size) {
    const float* enc  = (const float*)d_in[0];
    const float* dec  = (const float*)d_in[1];
    const float* Wa_w = (const float*)d_in[2];
    const float* Wa_b = (const float*)d_in[3];
    const float* Ua_w = (const float*)d_in[4];
    const float* Ua_b = (const float*)d_in[5];
    const float* Va_w = (const float*)d_in[6];
    const float* Va_b = (const float*)d_in[7];

    float* out = (float*)d_out;
    float* ctx = out;               // context [B,1,H]
    float* wts = out + BB * HH;     // attention weights [B,S]

    cudaFuncSetAttribute(energy_gemm_hmma,
                         cudaFuncAttributeMaxDynamicSharedMemorySize, GEMM_SMEM);

    split_ua_kernel<<<(HH * (HH / 4)) / 256, 256>>>(Ua_w);
    qc_kernel<<<HH / 8, 256>>>(dec, Wa_w, Wa_b, Ua_b);

    dim3 g(NT, MTOT / 128);   // (8, 512); o-tile fastest -> A panel L2 reuse
    energy_gemm_hmma<<<g, 256, GEMM_SMEM>>>(enc, Va_w);

    sparsemax_kernel<<<BB, 256>>>(Va_b, wts);

    dim3 gc(HH / 256, BB, SCH);
    context_part<<<gc, 256>>>(enc, wts);
    context_reduce<<<(BB * HH) / 256, 256>>>(ctx);
}

// round 16
// speedup vs baseline: 1.0260x; 1.0260x over previous
#include <cuda_runtime.h>
#include <cuda_bf16.h>
#include <stdint.h>

#define BB 32
#define SS 2048
#define HH 1024
#define MTOT (BB*SS)
#define NT 8            // 128-wide o-tiles
#define KC 32           // k per stage (bf16)
#define NKT (HH/KC)     // 32

// smem: A hi/lo 2-stage ring (16KB/stage), B hi/lo 4-stage ring (16KB/stage)
#define HALF 8192                   // one 128x32 bf16 tile (64B rows)
#define A_STAGE 16384               // Ah+Al
#define B_BASE  32768
#define B_STAGE 16384               // Bh+Bl
#define OF_VA   98304
#define OF_QC   (OF_VA+512)
#define OF_PART (OF_QC+512)
#define GEMM_SMEM (OF_PART+1024)    // 100352

#define SWZ(o) ((o) ^ (((o) >> 3) & 0x70))

// ---------------- device scratch (no allocs allowed) ----------------
__device__ float g_qc[BB*HH];
__device__ float g_part[NT][MTOT];
__device__ __nv_bfloat16 g_uhi[HH*HH];
__device__ __nv_bfloat16 g_ulo[HH*HH];
__device__ int   g_nnz[BB];
__device__ int   g_sidx[BB][SS];
__device__ float g_sw[BB][SS];

// ---------------- helpers ----------------
__device__ __forceinline__ uint32_t smem_u32(const void* p) {
    uint32_t a;
    asm("{ .reg .u64 t; cvta.to.shared.u64 t, %1; cvt.u32.u64 %0, t; }" : "=r"(a) : "l"(p));
    return a;
}
__device__ __forceinline__ void ldsm4(uint32_t a, uint32_t& r0, uint32_t& r1,
                                      uint32_t& r2, uint32_t& r3) {
    asm volatile("ldmatrix.sync.aligned.m8n8.x4.shared.b16 {%0,%1,%2,%3}, [%4];"
                 : "=r"(r0), "=r"(r1), "=r"(r2), "=r"(r3) : "r"(a));
}
__device__ __forceinline__ void mma16816(float* d, const uint32_t* a, uint32_t b0, uint32_t b1) {
    asm volatile("mma.sync.aligned.m16n8k16.row.col.f32.bf16.bf16.f32 "
                 "{%0,%1,%2,%3}, {%4,%5,%6,%7}, {%8,%9}, {%0,%1,%2,%3};"
                 : "+f"(d[0]), "+f"(d[1]), "+f"(d[2]), "+f"(d[3])
                 : "r"(a[0]), "r"(a[1]), "r"(a[2]), "r"(a[3]), "r"(b0), "r"(b1));
}
// flag-independent tanh: 1 - 2/(1+e^{2x}); exact saturation at +/-inf.
__device__ __forceinline__ float tanh_fast(float x) {
    float e;
    asm("ex2.approx.f32 %0, %1;" : "=f"(e) : "f"(x * 2.8853900817779268f));
    return 1.f - __fdividef(2.f, 1.f + e);
}
// pack two fp32 -> (bf16 hi pair, bf16 lo pair)
__device__ __forceinline__ void hilo2(float x, float y, uint32_t& hp, uint32_t& lp) {
    uint32_t h;
    asm("cvt.rn.bf16x2.f32 %0, %1, %2;" : "=r"(h) : "f"(y), "f"(x));  // {hi=y, lo=x}
    float hx = __uint_as_float(h << 16);
    float hy = __uint_as_float(h & 0xFFFF0000u);
    float lx = x - hx, ly = y - hy;
    uint32_t l;
    asm("cvt.rn.bf16x2.f32 %0, %1, %2;" : "=r"(l) : "f"(ly), "f"(lx));
    hp = h; lp = l;
}

// ---------------- kernel 0: Ua fp32 -> bf16 hi/lo split (4MB) --------------
__global__ void split_ua_kernel(const float* __restrict__ src) {
    int i = blockIdx.x * 256 + threadIdx.x;
    float4 v = ((const float4*)src)[i];
    uint2 ph, pl;
    hilo2(v.x, v.y, ph.x, pl.x);
    hilo2(v.z, v.w, ph.y, pl.y);
    ((uint2*)g_uhi)[i] = ph;
    ((uint2*)g_ulo)[i] = pl;
}

// ---------------- kernel 1: qc[b,o] = dec@Wa^T + Wa_b + Ua_b ----------------
__global__ void qc_kernel(const float* __restrict__ dec,
                          const float* __restrict__ Wa_w,
                          const float* __restrict__ Wa_b,
                          const float* __restrict__ Ua_b) {
    int gw = (blockIdx.x * blockDim.x + threadIdx.x) >> 5;
    int lane = threadIdx.x & 31;
    if (gw >= BB * HH) return;
    int b = gw >> 10;
    int o = gw & (HH - 1);
    const float* dr = dec + b * HH;
    const float* wr = Wa_w + o * HH;
    float s = 0.f;
    #pragma unroll 8
    for (int h = lane; h < HH; h += 32) s = fmaf(dr[h], wr[h], s);
    #pragma unroll
    for (int off = 16; off; off >>= 1) s += __shfl_xor_sync(0xffffffffu, s, off);
    if (lane == 0) g_qc[gw] = s + Wa_b[o] + Ua_b[o];
}

// ---------------- kernel 2: HMMA energy GEMM (bf16x3, fused A split) --------
// UNCHANGED from the 947us winner.
__global__ __launch_bounds__(256, 2)
void energy_gemm_hmma(const float* __restrict__ enc, const float* __restrict__ Va) {
    extern __shared__ __align__(1024) char smem[];
    uint32_t sb = smem_u32(smem);
    const int tid = threadIdx.x, wid = tid >> 5, lane = tid & 31;
    const int ot = blockIdx.x, m0 = blockIdx.y * 128, o0 = ot * 128;
    const int b = m0 >> 11;                 // / SS
    const int wm = wid & 3, wn = wid >> 2;  // warp grid 4x2
    const int tT = lane >> 3, r8 = lane & 7;

    if (tid < 128) {
        ((float*)(smem + OF_VA))[tid] = Va[o0 + tid];
        ((float*)(smem + OF_QC))[tid] = g_qc[b * HH + o0 + tid];
    }

    const float* gA = enc + (size_t)m0 * HH;          // fp32 A panel
    const __nv_bfloat16* gBh = g_uhi + (size_t)o0 * HH;
    const __nv_bfloat16* gBl = g_ulo + (size_t)o0 * HH;

    const int ar[4] = { (tid + 0) >> 3, (tid + 256) >> 3, (tid + 512) >> 3, (tid + 768) >> 3 };
    const int ac4   =  tid & 7;

    auto ldgA = [&](int kt, float4* regs) {
        #pragma unroll
        for (int t = 0; t < 4; ++t)
            regs[t] = *(const float4*)(gA + (size_t)ar[t] * HH + kt * KC + ac4 * 4);
    };
    auto stsA = [&](int st, const float4* regs) {
        uint32_t base = sb + st * A_STAGE;
        #pragma unroll
        for (int t = 0; t < 4; ++t) {
            uint32_t off = SWZ((uint32_t)(ar[t] * 64 + (ac4 >> 1) * 16)) + (ac4 & 1) * 8;
            uint32_t h0, l0, h1, l1;
            hilo2(regs[t].x, regs[t].y, h0, l0);
            hilo2(regs[t].z, regs[t].w, h1, l1);
            asm volatile("st.shared.v2.b32 [%0], {%1,%2};" :: "r"(base + off), "r"(h0), "r"(h1) : "memory");
            asm volatile("st.shared.v2.b32 [%0], {%1,%2};" :: "r"(base + HALF + off), "r"(l0), "r"(l1) : "memory");
        }
    };
    auto issueB = [&](int st4, int kt) {
        #pragma unroll
        for (int t = 0; t < 4; ++t) {
            const int arr = t >> 1;                     // 0: Bh, 1: Bl
            int idx = ((t & 1) << 8) + tid;             // 0..511 per tile
            int r = idx >> 2, c = idx & 3;
            const __nv_bfloat16* g = (arr ? gBl : gBh) + (size_t)r * HH + kt * KC + c * 8;
            uint32_t s = sb + B_BASE + st4 * B_STAGE + arr * HALF + SWZ((uint32_t)(r * 64 + c * 16));
            asm volatile("cp.async.cg.shared.global [%0], [%1], 16;" :: "r"(s), "l"(g));
        }
        asm volatile("cp.async.commit_group;" ::: "memory");
    };

    float acc[2][8][4];
    #pragma unroll
    for (int i = 0; i < 2; ++i)
        #pragma unroll
        for (int j = 0; j < 8; ++j)
            #pragma unroll
            for (int k = 0; k < 4; ++k) acc[i][j][k] = 0.f;

    float4 aReg[4];
    ldgA(0, aReg);
    issueB(0, 0);
    stsA(0, aReg);          // A(0) into buf 0 (published by loop's first barrier)
    ldgA(1, aReg);
    issueB(1, 1);
    issueB(2, 2);

    for (int kt = 0; kt < NKT; ++kt) {
        asm volatile("cp.async.wait_group 2;" ::: "memory");
        __syncthreads();   // publish A(kt)+B(kt); all warps past compute(kt-1)
        if (kt + 3 < NKT)
            issueB((kt + 3) & 3, kt + 3);
        else
            asm volatile("cp.async.commit_group;" ::: "memory");  // keep group math exact

        uint32_t stbA = sb + (uint32_t)(kt & 1) * A_STAGE;
        uint32_t stbB = sb + B_BASE + (uint32_t)(kt & 3) * B_STAGE;

        auto computeHalf = [&](int kk) {
            uint32_t ah[2][4], al[2][4];
            #pragma unroll
            for (int mb = 0; mb < 2; ++mb) {
                uint32_t row  = wm * 32 + mb * 16 + (tT & 1) * 8 + r8;
                uint32_t byte = row * 64 + (kk * 16 + (tT >> 1) * 8) * 2;
                ldsm4(stbA + SWZ(byte), ah[mb][0], ah[mb][1], ah[mb][2], ah[mb][3]);
                ldsm4(stbA + HALF + SWZ(byte), al[mb][0], al[mb][1], al[mb][2], al[mb][3]);
            }
            uint32_t bh[2][4], bl[2][4];
            auto loadB = [&](int q, uint32_t* BH, uint32_t* BL) {
                uint32_t nrow = wn * 64 + q * 16 + (tT >> 1) * 8 + r8;
                uint32_t byte = nrow * 64 + (kk * 16 + (tT & 1) * 8) * 2;
                ldsm4(stbB + SWZ(byte), BH[0], BH[1], BH[2], BH[3]);
                ldsm4(stbB + HALF + SWZ(byte), BL[0], BL[1], BL[2], BL[3]);
            };
            loadB(0, bh[0], bl[0]);
            #pragma unroll
            for (int q = 0; q < 4; ++q) {
                if (q < 3) loadB(q + 1, bh[(q + 1) & 1], bl[(q + 1) & 1]);
                const uint32_t* BH = bh[q & 1];
                const uint32_t* BL = bl[q & 1];
                #pragma unroll
                for (int mb = 0; mb < 2; ++mb) {
                    mma16816(acc[mb][2 * q + 0], ah[mb], BH[0], BH[1]);   // Ah*Bh
                    mma16816(acc[mb][2 * q + 1], ah[mb], BH[2], BH[3]);
                    mma16816(acc[mb][2 * q + 0], ah[mb], BL[0], BL[1]);   // Ah*Bl
                    mma16816(acc[mb][2 * q + 1], ah[mb], BL[2], BL[3]);
                    mma16816(acc[mb][2 * q + 0], al[mb], BH[0], BH[1]);   // Al*Bh
                    mma16816(acc[mb][2 * q + 1], al[mb], BH[2], BH[3]);
                }
            }
        };
        computeHalf(0);
        // A staging mid-loop: off the barrier->MMA critical path. stsA(kt+1)
        // reads aReg BEFORE ldgA(kt+2) overwrites it (WAR order).
        if (kt + 1 < NKT) stsA((kt + 1) & 1, aReg);
        if (kt + 2 < NKT) ldgA(kt + 2, aReg);
        computeHalf(1);
    }

    // Fused epilogue: part[m] = sum_o Va[o]*tanh(acc + qc[o])
    const float* sva = (const float*)(smem + OF_VA);
    const float* sqc = (const float*)(smem + OF_QC);
    const int gid = lane >> 2, t4 = lane & 3;
    float pm[4] = {0.f, 0.f, 0.f, 0.f};
    #pragma unroll
    for (int mb = 0; mb < 2; ++mb)
        #pragma unroll
        for (int nb = 0; nb < 8; ++nb) {
            int o = wn * 64 + nb * 8 + t4 * 2;
            float va0 = sva[o], va1 = sva[o + 1];
            float q0 = sqc[o], q1 = sqc[o + 1];
            pm[mb * 2 + 0] += va0 * tanh_fast(acc[mb][nb][0] + q0)
                            + va1 * tanh_fast(acc[mb][nb][1] + q1);
            pm[mb * 2 + 1] += va0 * tanh_fast(acc[mb][nb][2] + q0)
                            + va1 * tanh_fast(acc[mb][nb][3] + q1);
        }
    #pragma unroll
    for (int off = 1; off <= 2; off <<= 1) {
        #pragma unroll
        for (int i = 0; i < 4; ++i) pm[i] += __shfl_xor_sync(0xffffffffu, pm[i], off);
    }
    float* sp = (float*)(smem + OF_PART);
    __syncthreads();
    if (t4 == 0) {
        #pragma unroll
        for (int mb = 0; mb < 2; ++mb) {
            sp[wn * 128 + wm * 32 + mb * 16 + gid]     = pm[mb * 2 + 0];
            sp[wn * 128 + wm * 32 + mb * 16 + 8 + gid] = pm[mb * 2 + 1];
        }
    }
    __syncthreads();
    if (tid < 128) g_part[ot][m0 + tid] = sp[tid] + sp[128 + tid];
}

// ---------------- kernel 3: sparsemax + deterministic support compaction ----
// tau math IDENTICAL to the 947us winner (20 bisection iters, tau=mid start,
// 2 Michelot refinements). Afterwards: ordered ballot/prefix compaction of
// the support into g_sidx/g_sw (ascending s -> deterministic, atomics-free).
__global__ void sparsemax_kernel(const float* __restrict__ Va_b,
                                 float* __restrict__ wout) {
    __shared__ float z[SS];
    __shared__ float red[33];
    __shared__ int   wcnt[9];
    const int b = blockIdx.x;
    const int tid = threadIdx.x;
    const int wid = tid >> 5, lane = tid & 31;
    const float vb = Va_b[0];

    for (int s = tid; s < SS; s += 256) {
        float e = vb;
        #pragma unroll
        for (int t = 0; t < NT; ++t) e += g_part[t][b * SS + s];
        z[s] = e;
    }
    __syncthreads();

    float mx = -3.4e38f;
    for (int s = tid; s < SS; s += 256) mx = fmaxf(mx, z[s]);
    #pragma unroll
    for (int off = 16; off; off >>= 1) mx = fmaxf(mx, __shfl_xor_sync(0xffffffffu, mx, off));
    if (lane == 0) red[wid] = mx;
    __syncthreads();
    if (tid == 0) {
        float m = red[0];
        for (int i = 1; i < 8; ++i) m = fmaxf(m, red[i]);
        red[32] = m;
    }
    __syncthreads();
    const float zmax = red[32];
    __syncthreads();

    float lo = zmax - 1.f, hi = zmax;
    for (int it = 0; it < 20; ++it) {
        float mid = 0.5f * (lo + hi);
        float sum = 0.f;
        for (int s = tid; s < SS; s += 256) sum += fmaxf(z[s] - mid, 0.f);
        #pragma unroll
        for (int off = 16; off; off >>= 1) sum += __shfl_xor_sync(0xffffffffu, sum, off);
        if (lane == 0) red[wid] = sum;
        __syncthreads();
        if (tid == 0) {
            float t = 0.f;
            for (int i = 0; i < 8; ++i) t += red[i];
            red[32] = t;
        }
        __syncthreads();
        float tot = red[32];
        __syncthreads();
        if (tot >= 1.f) lo = mid; else hi = mid;
    }
    float tau = 0.5f * (lo + hi);

    for (int r2 = 0; r2 < 2; ++r2) {
        float cnt = 0.f, ssum = 0.f;
        for (int s = tid; s < SS; s += 256) {
            float zv = z[s];
            if (zv > tau) { cnt += 1.f; ssum += zv; }
        }
        #pragma unroll
        for (int off = 16; off; off >>= 1) {
            cnt  += __shfl_xor_sync(0xffffffffu, cnt,  off);
            ssum += __shfl_xor_sync(0xffffffffu, ssum, off);
        }
        if (lane == 0) { red[wid] = cnt; red[8 + wid] = ssum; }
        __syncthreads();
        if (tid == 0) {
            float c = 0.f, s2 = 0.f;
            for (int i = 0; i < 8; ++i) { c += red[i]; s2 += red[8 + i]; }
            red[32] = (s2 - 1.f) / c;
        }
        __syncthreads();
        tau = red[32];
        __syncthreads();
    }

    // write weights + ordered compaction (8 chunks of 256, ascending s)
    int base = 0;
    for (int c = 0; c < 8; ++c) {
        int s = c * 256 + tid;
        float w = fmaxf(z[s] - tau, 0.f);
        wout[b * SS + s] = w;
        bool pred = (w != 0.f);
        uint32_t ball = __ballot_sync(0xffffffffu, pred);
        int wpre = __popc(ball & ((1u << lane) - 1));
        if (lane == 0) wcnt[wid] = __popc(ball);
        __syncthreads();
        if (tid == 0) {
            int acc2 = 0;
            #pragma unroll
            for (int i = 0; i < 8; ++i) { int t = wcnt[i]; wcnt[i] = acc2; acc2 += t; }
            wcnt[8] = acc2;
        }
        __syncthreads();
        if (pred) {
            int pos = base + wcnt[wid] + wpre;
            g_sidx[b][pos] = s;
            g_sw[b][pos] = w;
        }
        base += wcnt[8];
        __syncthreads();
    }
    if (tid == 0) g_nnz[b] = base;
}

// ---------------- kernel 4: sparse context over the compacted support ------
// ctx[b,h] = sum_i w_i * enc[b, sidx_i, h], ascending i (same order as the
// old dense s-loop -> bit-identical sums).
__global__ void context_sparse(const float* __restrict__ enc,
                               float* __restrict__ ctx) {
    __shared__ float sw[256];
    __shared__ int   si[256];
    const int b = blockIdx.y;
    const int h = blockIdx.x * 256 + threadIdx.x;
    const int tid = threadIdx.x;
    const int nnz = g_nnz[b];
    const float* e = enc + (size_t)b * SS * HH + h;
    float acc = 0.f;
    for (int base = 0; base < nnz; base += 256) {
        int n = min(256, nnz - base);
        if (tid < n) { sw[tid] = g_sw[b][base + tid]; si[tid] = g_sidx[b][base + tid]; }
        __syncthreads();
        for (int i = 0; i < n; ++i)
            acc = fmaf(sw[i], e[(size_t)si[i] * HH], acc);
        __syncthreads();
    }
    ctx[b * HH + h] = acc;
}

// ---------------------------------------------------------------------------
extern "C" void kernel_launch(void* const* d_in, const int* in_sizes, int n_in,
                              void* d_out, int out_size) {
    const float* enc  = (const float*)d_in[0];
    const float* dec  = (const float*)d_in[1];
    const float* Wa_w = (const float*)d_in[2];
    const float* Wa_b = (const float*)d_in[3];
    const float* Ua_w = (const float*)d_in[4];
    const float* Ua_b = (const float*)d_in[5];
    const float* Va_w = (const float*)d_in[6];
    const float* Va_b = (const float*)d_in[7];

    float* out = (float*)d_out;
    float* ctx = out;               // context [B,1,H]
    float* wts = out + BB * HH;     // attention weights [B,S]

    cudaFuncSetAttribute(energy_gemm_hmma,
                         cudaFuncAttributeMaxDynamicSharedMemorySize, GEMM_SMEM);

    split_ua_kernel<<<(HH * (HH / 4)) / 256, 256>>>(Ua_w);
    qc_kernel<<<(BB * HH) / 8, 256>>>(dec, Wa_w, Wa_b, Ua_b);

    dim3 g(NT, MTOT / 128);   // (8, 512); o-tile fastest -> A panel L2 reuse
    energy_gemm_hmma<<<g, 256, GEMM_SMEM>>>(enc, Va_w);

    sparsemax_kernel<<<BB, 256>>>(Va_b, wts);

    dim3 gc(HH / 256, BB);
    context_sparse<<<gc, 256>>>(enc, ctx);
}

// round 17
// speedup vs baseline: 1.0265x; 1.0005x over previous
#include <cuda_runtime.h>
#include <cuda_bf16.h>
#include <stdint.h>

#define BB 32
#define SS 2048
#define HH 1024
#define MTOT (BB*SS)
#define NT 8            // 128-wide o-tiles
#define KC 32           // k per stage (bf16)
#define NKT (HH/KC)     // 32

// smem: A hi/lo 2-stage ring (16KB/stage), B hi/lo 4-stage ring (16KB/stage)
#define HALF 8192                   // one 128x32 bf16 tile (64B rows)
#define A_STAGE 16384               // Ah+Al
#define B_BASE  32768
#define B_STAGE 16384               // Bh+Bl
#define OF_VA   98304
#define OF_QC   (OF_VA+512)
#define OF_PART (OF_QC+512)
#define GEMM_SMEM (OF_PART+1024)    // 100352

#define SWZ(o) ((o) ^ (((o) >> 3) & 0x70))

// ---------------- device scratch (no allocs allowed) ----------------
__device__ float g_qc[BB*HH];
__device__ float g_part[NT][MTOT];
__device__ __nv_bfloat16 g_uhi[HH*HH];
__device__ __nv_bfloat16 g_ulo[HH*HH];
__device__ int   g_nnz[BB];
__device__ int   g_sidx[BB][SS];
__device__ float g_sw[BB][SS];

// ---------------- helpers ----------------
__device__ __forceinline__ uint32_t smem_u32(const void* p) {
    uint32_t a;
    asm("{ .reg .u64 t; cvta.to.shared.u64 t, %1; cvt.u32.u64 %0, t; }" : "=r"(a) : "l"(p));
    return a;
}
__device__ __forceinline__ void ldsm4(uint32_t a, uint32_t& r0, uint32_t& r1,
                                      uint32_t& r2, uint32_t& r3) {
    asm volatile("ldmatrix.sync.aligned.m8n8.x4.shared.b16 {%0,%1,%2,%3}, [%4];"
                 : "=r"(r0), "=r"(r1), "=r"(r2), "=r"(r3) : "r"(a));
}
__device__ __forceinline__ void mma16816(float* d, const uint32_t* a, uint32_t b0, uint32_t b1) {
    asm volatile("mma.sync.aligned.m16n8k16.row.col.f32.bf16.bf16.f32 "
                 "{%0,%1,%2,%3}, {%4,%5,%6,%7}, {%8,%9}, {%0,%1,%2,%3};"
                 : "+f"(d[0]), "+f"(d[1]), "+f"(d[2]), "+f"(d[3])
                 : "r"(a[0]), "r"(a[1]), "r"(a[2]), "r"(a[3]), "r"(b0), "r"(b1));
}
// flag-independent tanh: 1 - 2/(1+e^{2x}); exact saturation at +/-inf.
__device__ __forceinline__ float tanh_fast(float x) {
    float e;
    asm("ex2.approx.f32 %0, %1;" : "=f"(e) : "f"(x * 2.8853900817779268f));
    return 1.f - __fdividef(2.f, 1.f + e);
}
// pack two fp32 -> (bf16 hi pair, bf16 lo pair)
__device__ __forceinline__ void hilo2(float x, float y, uint32_t& hp, uint32_t& lp) {
    uint32_t h;
    asm("cvt.rn.bf16x2.f32 %0, %1, %2;" : "=r"(h) : "f"(y), "f"(x));  // {hi=y, lo=x}
    float hx = __uint_as_float(h << 16);
    float hy = __uint_as_float(h & 0xFFFF0000u);
    float lx = x - hx, ly = y - hy;
    uint32_t l;
    asm("cvt.rn.bf16x2.f32 %0, %1, %2;" : "=r"(l) : "f"(ly), "f"(lx));
    hp = h; lp = l;
}

// ---------------- kernel 0: Ua fp32 -> bf16 hi/lo split (4MB) --------------
__global__ void split_ua_kernel(const float* __restrict__ src) {
    int i = blockIdx.x * 256 + threadIdx.x;
    float4 v = ((const float4*)src)[i];
    uint2 ph, pl;
    hilo2(v.x, v.y, ph.x, pl.x);
    hilo2(v.z, v.w, ph.y, pl.y);
    ((uint2*)g_uhi)[i] = ph;
    ((uint2*)g_ulo)[i] = pl;
}

// ---------------- kernel 1: qc[b,o] = dec@Wa^T + Wa_b + Ua_b ----------------
// One warp per (o, group of 4 b): Wa row held in 32 regs, reused 4x ->
// Wa traffic 128MB -> 32MB. Per-lane FMA order identical to the old kernel
// (j ascending, same shfl tree) -> bit-identical qc.
__global__ void qc_kernel(const float* __restrict__ dec,
                          const float* __restrict__ Wa_w,
                          const float* __restrict__ Wa_b,
                          const float* __restrict__ Ua_b) {
    int gw = (blockIdx.x * blockDim.x + threadIdx.x) >> 5;   // 0..8191
    int lane = threadIdx.x & 31;
    int o  = gw >> 3;           // 0..1023
    int bg = (gw & 7) << 2;     // batch base: 0,4,...,28
    const float* wr = Wa_w + o * HH;

    float wa[32];
    #pragma unroll
    for (int j = 0; j < 32; ++j) wa[j] = wr[j * 32 + lane];

    float acc[4] = {0.f, 0.f, 0.f, 0.f};
    #pragma unroll
    for (int v = 0; v < 4; ++v) {
        const float* dr = dec + (bg + v) * HH;
        #pragma unroll
        for (int j = 0; j < 32; ++j)
            acc[v] = fmaf(dr[j * 32 + lane], wa[j], acc[v]);
    }
    #pragma unroll
    for (int off = 16; off; off >>= 1)
        #pragma unroll
        for (int v = 0; v < 4; ++v)
            acc[v] += __shfl_xor_sync(0xffffffffu, acc[v], off);
    if (lane == 0) {
        float bias = Wa_b[o] + Ua_b[o];
        #pragma unroll
        for (int v = 0; v < 4; ++v)
            g_qc[(bg + v) * HH + o] = acc[v] + bias;
    }
}

// ---------------- kernel 2: HMMA energy GEMM (bf16x3, fused A split) --------
// UNCHANGED from the 930us winner.
__global__ __launch_bounds__(256, 2)
void energy_gemm_hmma(const float* __restrict__ enc, const float* __restrict__ Va) {
    extern __shared__ __align__(1024) char smem[];
    uint32_t sb = smem_u32(smem);
    const int tid = threadIdx.x, wid = tid >> 5, lane = tid & 31;
    const int ot = blockIdx.x, m0 = blockIdx.y * 128, o0 = ot * 128;
    const int b = m0 >> 11;                 // / SS
    const int wm = wid & 3, wn = wid >> 2;  // warp grid 4x2
    const int tT = lane >> 3, r8 = lane & 7;

    if (tid < 128) {
        ((float*)(smem + OF_VA))[tid] = Va[o0 + tid];
        ((float*)(smem + OF_QC))[tid] = g_qc[b * HH + o0 + tid];
    }

    const float* gA = enc + (size_t)m0 * HH;          // fp32 A panel
    const __nv_bfloat16* gBh = g_uhi + (size_t)o0 * HH;
    const __nv_bfloat16* gBl = g_ulo + (size_t)o0 * HH;

    const int ar[4] = { (tid + 0) >> 3, (tid + 256) >> 3, (tid + 512) >> 3, (tid + 768) >> 3 };
    const int ac4   =  tid & 7;

    auto ldgA = [&](int kt, float4* regs) {
        #pragma unroll
        for (int t = 0; t < 4; ++t)
            regs[t] = *(const float4*)(gA + (size_t)ar[t] * HH + kt * KC + ac4 * 4);
    };
    auto stsA = [&](int st, const float4* regs) {
        uint32_t base = sb + st * A_STAGE;
        #pragma unroll
        for (int t = 0; t < 4; ++t) {
            uint32_t off = SWZ((uint32_t)(ar[t] * 64 + (ac4 >> 1) * 16)) + (ac4 & 1) * 8;
            uint32_t h0, l0, h1, l1;
            hilo2(regs[t].x, regs[t].y, h0, l0);
            hilo2(regs[t].z, regs[t].w, h1, l1);
            asm volatile("st.shared.v2.b32 [%0], {%1,%2};" :: "r"(base + off), "r"(h0), "r"(h1) : "memory");
            asm volatile("st.shared.v2.b32 [%0], {%1,%2};" :: "r"(base + HALF + off), "r"(l0), "r"(l1) : "memory");
        }
    };
    auto issueB = [&](int st4, int kt) {
        #pragma unroll
        for (int t = 0; t < 4; ++t) {
            const int arr = t >> 1;                     // 0: Bh, 1: Bl
            int idx = ((t & 1) << 8) + tid;             // 0..511 per tile
            int r = idx >> 2, c = idx & 3;
            const __nv_bfloat16* g = (arr ? gBl : gBh) + (size_t)r * HH + kt * KC + c * 8;
            uint32_t s = sb + B_BASE + st4 * B_STAGE + arr * HALF + SWZ((uint32_t)(r * 64 + c * 16));
            asm volatile("cp.async.cg.shared.global [%0], [%1], 16;" :: "r"(s), "l"(g));
        }
        asm volatile("cp.async.commit_group;" ::: "memory");
    };

    float acc[2][8][4];
    #pragma unroll
    for (int i = 0; i < 2; ++i)
        #pragma unroll
        for (int j = 0; j < 8; ++j)
            #pragma unroll
            for (int k = 0; k < 4; ++k) acc[i][j][k] = 0.f;

    float4 aReg[4];
    ldgA(0, aReg);
    issueB(0, 0);
    stsA(0, aReg);          // A(0) into buf 0 (published by loop's first barrier)
    ldgA(1, aReg);
    issueB(1, 1);
    issueB(2, 2);

    for (int kt = 0; kt < NKT; ++kt) {
        asm volatile("cp.async.wait_group 2;" ::: "memory");
        __syncthreads();   // publish A(kt)+B(kt); all warps past compute(kt-1)
        if (kt + 3 < NKT)
            issueB((kt + 3) & 3, kt + 3);
        else
            asm volatile("cp.async.commit_group;" ::: "memory");  // keep group math exact

        uint32_t stbA = sb + (uint32_t)(kt & 1) * A_STAGE;
        uint32_t stbB = sb + B_BASE + (uint32_t)(kt & 3) * B_STAGE;

        auto computeHalf = [&](int kk) {
            uint32_t ah[2][4], al[2][4];
            #pragma unroll
            for (int mb = 0; mb < 2; ++mb) {
                uint32_t row  = wm * 32 + mb * 16 + (tT & 1) * 8 + r8;
                uint32_t byte = row * 64 + (kk * 16 + (tT >> 1) * 8) * 2;
                ldsm4(stbA + SWZ(byte), ah[mb][0], ah[mb][1], ah[mb][2], ah[mb][3]);
                ldsm4(stbA + HALF + SWZ(byte), al[mb][0], al[mb][1], al[mb][2], al[mb][3]);
            }
            uint32_t bh[2][4], bl[2][4];
            auto loadB = [&](int q, uint32_t* BH, uint32_t* BL) {
                uint32_t nrow = wn * 64 + q * 16 + (tT >> 1) * 8 + r8;
                uint32_t byte = nrow * 64 + (kk * 16 + (tT & 1) * 8) * 2;
                ldsm4(stbB + SWZ(byte), BH[0], BH[1], BH[2], BH[3]);
                ldsm4(stbB + HALF + SWZ(byte), BL[0], BL[1], BL[2], BL[3]);
            };
            loadB(0, bh[0], bl[0]);
            #pragma unroll
            for (int q = 0; q < 4; ++q) {
                if (q < 3) loadB(q + 1, bh[(q + 1) & 1], bl[(q + 1) & 1]);
                const uint32_t* BH = bh[q & 1];
                const uint32_t* BL = bl[q & 1];
                #pragma unroll
                for (int mb = 0; mb < 2; ++mb) {
                    mma16816(acc[mb][2 * q + 0], ah[mb], BH[0], BH[1]);   // Ah*Bh
                    mma16816(acc[mb][2 * q + 1], ah[mb], BH[2], BH[3]);
                    mma16816(acc[mb][2 * q + 0], ah[mb], BL[0], BL[1]);   // Ah*Bl
                    mma16816(acc[mb][2 * q + 1], ah[mb], BL[2], BL[3]);
                    mma16816(acc[mb][2 * q + 0], al[mb], BH[0], BH[1]);   // Al*Bh
                    mma16816(acc[mb][2 * q + 1], al[mb], BH[2], BH[3]);
                }
            }
        };
        computeHalf(0);
        // A staging mid-loop: off the barrier->MMA critical path. stsA(kt+1)
        // reads aReg BEFORE ldgA(kt+2) overwrites it (WAR order).
        if (kt + 1 < NKT) stsA((kt + 1) & 1, aReg);
        if (kt + 2 < NKT) ldgA(kt + 2, aReg);
        computeHalf(1);
    }

    // Fused epilogue: part[m] = sum_o Va[o]*tanh(acc + qc[o])
    const float* sva = (const float*)(smem + OF_VA);
    const float* sqc = (const float*)(smem + OF_QC);
    const int gid = lane >> 2, t4 = lane & 3;
    float pm[4] = {0.f, 0.f, 0.f, 0.f};
    #pragma unroll
    for (int mb = 0; mb < 2; ++mb)
        #pragma unroll
        for (int nb = 0; nb < 8; ++nb) {
            int o = wn * 64 + nb * 8 + t4 * 2;
            float va0 = sva[o], va1 = sva[o + 1];
            float q0 = sqc[o], q1 = sqc[o + 1];
            pm[mb * 2 + 0] += va0 * tanh_fast(acc[mb][nb][0] + q0)
                            + va1 * tanh_fast(acc[mb][nb][1] + q1);
            pm[mb * 2 + 1] += va0 * tanh_fast(acc[mb][nb][2] + q0)
                            + va1 * tanh_fast(acc[mb][nb][3] + q1);
        }
    #pragma unroll
    for (int off = 1; off <= 2; off <<= 1) {
        #pragma unroll
        for (int i = 0; i < 4; ++i) pm[i] += __shfl_xor_sync(0xffffffffu, pm[i], off);
    }
    float* sp = (float*)(smem + OF_PART);
    __syncthreads();
    if (t4 == 0) {
        #pragma unroll
        for (int mb = 0; mb < 2; ++mb) {
            sp[wn * 128 + wm * 32 + mb * 16 + gid]     = pm[mb * 2 + 0];
            sp[wn * 128 + wm * 32 + mb * 16 + 8 + gid] = pm[mb * 2 + 1];
        }
    }
    __syncthreads();
    if (tid < 128) g_part[ot][m0 + tid] = sp[tid] + sp[128 + tid];
}

// ---------------- kernel 3: sparsemax + compaction (warp-level bisection) ---
// z assembly + weight write + compaction unchanged. Max/bisection/refinement
// run entirely in warp 0 (64 z per lane in regs, 5-level shfl, zero barriers,
// uniform branches), then tau broadcast once.
__global__ void sparsemax_kernel(const float* __restrict__ Va_b,
                                 float* __restrict__ wout) {
    __shared__ float z[SS];
    __shared__ float stau;
    __shared__ int   wcnt[9];
    const int b = blockIdx.x;
    const int tid = threadIdx.x;
    const int wid = tid >> 5, lane = tid & 31;
    const float vb = Va_b[0];

    for (int s = tid; s < SS; s += 256) {
        float e = vb;
        #pragma unroll
        for (int t = 0; t < NT; ++t) e += g_part[t][b * SS + s];
        z[s] = e;
    }
    __syncthreads();

    if (wid == 0) {
        float zr[64];
        #pragma unroll
        for (int j = 0; j < 64; ++j) zr[j] = z[j * 32 + lane];

        float mx = zr[0];
        #pragma unroll
        for (int j = 1; j < 64; ++j) mx = fmaxf(mx, zr[j]);
        #pragma unroll
        for (int off = 16; off; off >>= 1)
            mx = fmaxf(mx, __shfl_xor_sync(0xffffffffu, mx, off));

        float lo = mx - 1.f, hi = mx;
        for (int it = 0; it < 20; ++it) {
            float mid = 0.5f * (lo + hi);
            float sum = 0.f;
            #pragma unroll
            for (int j = 0; j < 64; ++j) sum += fmaxf(zr[j] - mid, 0.f);
            #pragma unroll
            for (int off = 16; off; off >>= 1)
                sum += __shfl_xor_sync(0xffffffffu, sum, off);
            if (sum >= 1.f) lo = mid; else hi = mid;   // uniform across warp
        }
        float tau = 0.5f * (lo + hi);

        for (int r2 = 0; r2 < 2; ++r2) {
            float cnt = 0.f, ssum = 0.f;
            #pragma unroll
            for (int j = 0; j < 64; ++j) {
                float zv = zr[j];
                if (zv > tau) { cnt += 1.f; ssum += zv; }
            }
            #pragma unroll
            for (int off = 16; off; off >>= 1) {
                cnt  += __shfl_xor_sync(0xffffffffu, cnt,  off);
                ssum += __shfl_xor_sync(0xffffffffu, ssum, off);
            }
            tau = (ssum - 1.f) / cnt;
        }
        if (lane == 0) stau = tau;
    }
    __syncthreads();
    const float tau = stau;

    // write weights + ordered compaction (8 chunks of 256, ascending s)
    int base = 0;
    for (int c = 0; c < 8; ++c) {
        int s = c * 256 + tid;
        float w = fmaxf(z[s] - tau, 0.f);
        wout[b * SS + s] = w;
        bool pred = (w != 0.f);
        uint32_t ball = __ballot_sync(0xffffffffu, pred);
        int wpre = __popc(ball & ((1u << lane) - 1));
        if (lane == 0) wcnt[wid] = __popc(ball);
        __syncthreads();
        if (tid == 0) {
            int acc2 = 0;
            #pragma unroll
            for (int i = 0; i < 8; ++i) { int t = wcnt[i]; wcnt[i] = acc2; acc2 += t; }
            wcnt[8] = acc2;
        }
        __syncthreads();
        if (pred) {
            int pos = base + wcnt[wid] + wpre;
            g_sidx[b][pos] = s;
            g_sw[b][pos] = w;
        }
        base += wcnt[8];
        __syncthreads();
    }
    if (tid == 0) g_nnz[b] = base;
}

// ---------------- kernel 4: sparse context over the compacted support ------
__global__ void context_sparse(const float* __restrict__ enc,
                               float* __restrict__ ctx) {
    __shared__ float sw[256];
    __shared__ int   si[256];
    const int b = blockIdx.y;
    const int h = blockIdx.x * 256 + threadIdx.x;
    const int tid = threadIdx.x;
    const int nnz = g_nnz[b];
    const float* e = enc + (size_t)b * SS * HH + h;
    float acc = 0.f;
    for (int base = 0; base < nnz; base += 256) {
        int n = min(256, nnz - base);
        if (tid < n) { sw[tid] = g_sw[b][base + tid]; si[tid] = g_sidx[b][base + tid]; }
        __syncthreads();
        for (int i = 0; i < n; ++i)
            acc = fmaf(sw[i], e[(size_t)si[i] * HH], acc);
        __syncthreads();
    }
    ctx[b * HH + h] = acc;
}

// ---------------------------------------------------------------------------
extern "C" void kernel_launch(void* const* d_in, const int* in_sizes, int n_in,
                              void* d_out, int out_size) {
    const float* enc  = (const float*)d_in[0];
    const float* dec  = (const float*)d_in[1];
    const float* Wa_w = (const float*)d_in[2];
    const float* Wa_b = (const float*)d_in[3];
    const float* Ua_w = (const float*)d_in[4];
    const float* Ua_b = (const float*)d_in[5];
    const float* Va_w = (const float*)d_in[6];
    const float* Va_b = (const float*)d_in[7];

    float* out = (float*)d_out;
    float* ctx = out;               // context [B,1,H]
    float* wts = out + BB * HH;     // attention weights [B,S]

    cudaFuncSetAttribute(energy_gemm_hmma,
                         cudaFuncAttributeMaxDynamicSharedMemorySize, GEMM_SMEM);

    split_ua_kernel<<<(HH * (HH / 4)) / 256, 256>>>(Ua_w);
    qc_kernel<<<(HH * 8 * 32) / 256, 256>>>(dec, Wa_w, Wa_b, Ua_b);   // 8192 warps

    dim3 g(NT, MTOT / 128);   // (8, 512); o-tile fastest -> A panel L2 reuse
    energy_gemm_hmma<<<g, 256, GEMM_SMEM>>>(enc, Va_w);

    sparsemax_kernel<<<BB, 256>>>(Va_b, wts);

    dim3 gc(HH / 256, BB);
    context_sparse<<<gc, 256>>>(enc, ctx);
}